// round 15
// baseline (speedup 1.0000x reference)
#include <cuda_runtime.h>

#define N_E   8192
#define E_DIM 512
#define B_SZ  8
#define T_SZ  1024
#define ROWS  (B_SZ * T_SZ)
#define CT    (E_DIM * T_SZ)
#define ZQ_ELEMS (B_SZ * E_DIM * T_SZ)

#define PITCH 40                         // halves per SMEM row (bf16 codebook kernel)
#define ARR_BYTES   10240
#define MARGIN 1.0f
#define SZ_Z  16.0f
#define SZ_CB 1024.0f
#define NEG2INV (-1.220703125e-4f)       // -2/(16*1024)

#define CB_STAGE (4 * ARR_BYTES)
#define SMEM_CB  (4096 + 2 * CB_STAGE)

// fp8 screen: A resident (8 chunks x 128 rows x 80B), B 2-stage
#define A_CHUNK 10240
#define B_BASE  (8 * A_CHUNK)            // 81920
#define SMEM_AG (B_BASE + 2 * A_CHUNK)   // 102400

// -------- scratch --------
__device__ float g_codebook[N_E * E_DIM];
__device__ float g_cbnorm[N_E];
__device__ float g_zf[ROWS * E_DIM];
__device__ unsigned char g_cb8[N_E * E_DIM];       // e4m3, scale 1024
__device__ unsigned char g_z8[ROWS * E_DIM];       // e4m3, scale 16
__device__ unsigned short g_e_h[N_E * E_DIM];
__device__ unsigned short g_e_l[N_E * E_DIM];
__device__ unsigned short g_w_h[E_DIM * E_DIM];
__device__ unsigned short g_w_l[E_DIM * E_DIM];
__device__ unsigned short g_scores[(size_t)ROWS * N_E];  // bf16 raw scaled dots
__device__ unsigned g_bmin[ROWS];                  // fkey(min screen score)
__device__ unsigned long long g_best[ROWS];
__device__ float g_partial[ROWS / 32];
__device__ int g_lo[B_SZ], g_hi[B_SZ];

__device__ __forceinline__ unsigned int fkey(float f) {
    unsigned int u = __float_as_uint(f);
    return (u & 0x80000000u) ? ~u : (u | 0x80000000u);
}
__device__ __forceinline__ float fkey_inv(unsigned u) {
    return __uint_as_float((u & 0x80000000u) ? (u ^ 0x80000000u) : ~u);
}
__device__ __forceinline__ unsigned short f2bf(float x) {
    unsigned u = __float_as_uint(x);
    unsigned rb = 0x7FFFu + ((u >> 16) & 1u);
    return (unsigned short)((u + rb) >> 16);
}
__device__ __forceinline__ float bf2f(unsigned short h) {
    return __uint_as_float(((unsigned)h) << 16);
}
__device__ __forceinline__ unsigned char f2e4(float x) {
    unsigned short v;
    asm("cvt.rn.satfinite.e4m3x2.f32 %0, %1, %1;" : "=h"(v) : "f"(x));
    return (unsigned char)(v & 0xFF);
}
__device__ __forceinline__ unsigned smem_u32(const void* p) {
    unsigned a;
    asm("{ .reg .u64 t; cvta.to.shared.u64 t, %1; cvt.u32.u64 %0, t; }" : "=r"(a) : "l"(p));
    return a;
}
__device__ __forceinline__ void mma_bf16(float* c, const unsigned* a, const unsigned* b) {
    asm volatile(
        "mma.sync.aligned.m16n8k16.row.col.f32.bf16.bf16.f32 "
        "{%0,%1,%2,%3}, {%4,%5,%6,%7}, {%8,%9}, {%0,%1,%2,%3};"
        : "+f"(c[0]), "+f"(c[1]), "+f"(c[2]), "+f"(c[3])
        : "r"(a[0]), "r"(a[1]), "r"(a[2]), "r"(a[3]), "r"(b[0]), "r"(b[1]));
}
__device__ __forceinline__ void mma_fp8(float* c, const unsigned* a, const unsigned* b) {
    asm volatile(
        "mma.sync.aligned.m16n8k32.row.col.f32.e4m3.e4m3.f32 "
        "{%0,%1,%2,%3}, {%4,%5,%6,%7}, {%8,%9}, {%0,%1,%2,%3};"
        : "+f"(c[0]), "+f"(c[1]), "+f"(c[2]), "+f"(c[3])
        : "r"(a[0]), "r"(a[1]), "r"(a[2]), "r"(a[3]), "r"(b[0]), "r"(b[1]));
}
__device__ __forceinline__ void ldsm4(unsigned* r, unsigned addr) {
    asm volatile("ldmatrix.sync.aligned.m8n8.x4.shared.b16 {%0,%1,%2,%3}, [%4];"
                 : "=r"(r[0]), "=r"(r[1]), "=r"(r[2]), "=r"(r[3]) : "r"(addr));
}
__device__ __forceinline__ void cp16(unsigned dst, const void* src) {
    asm volatile("cp.async.cg.shared.global [%0], [%1], 16;" :: "r"(dst), "l"(src));
}
#define CP_COMMIT() asm volatile("cp.async.commit_group;" ::: "memory")
#define CP_WAIT0()  asm volatile("cp.async.wait_group 0;" ::: "memory")
#define BARQ(id) asm volatile("bar.sync %0, 64;" :: "r"(id) : "memory")

// ======== L1: fused splits + setup ========
#define EBLK (N_E * E_DIM / 4 / 256)     // 4096
#define WBLK (E_DIM * E_DIM / 4 / 256)   // 256
#define ZBLK 4096
#define SBLK (N_E / 256)                 // 32 (setup blocks)
__global__ __launch_bounds__(256) void k_split_all(const float* __restrict__ emb,
                                                   const float* __restrict__ pw,
                                                   const float* __restrict__ z,
                                                   const int* __restrict__ ad) {
    const int blk = blockIdx.x;
    const int tid = threadIdx.x;
    if (blk < EBLK) {
        int i = blk * 256 + tid;
        float4 v = ((const float4*)emb)[i];
        float xs[4] = {v.x, v.y, v.z, v.w};
        ushort4 h, l;
        unsigned short* hp = &h.x; unsigned short* lp = &l.x;
#pragma unroll
        for (int j = 0; j < 4; j++) {
            unsigned short hh = f2bf(xs[j]);
            hp[j] = hh; lp[j] = f2bf(xs[j] - bf2f(hh));
        }
        *(ushort4*)&g_e_h[(size_t)i * 4] = h;
        *(ushort4*)&g_e_l[(size_t)i * 4] = l;
    } else if (blk < EBLK + WBLK) {
        int i = (blk - EBLK) * 256 + tid;
        float4 v = ((const float4*)pw)[i];
        float xs[4] = {v.x, v.y, v.z, v.w};
        ushort4 h, l;
        unsigned short* hp = &h.x; unsigned short* lp = &l.x;
#pragma unroll
        for (int j = 0; j < 4; j++) {
            unsigned short hh = f2bf(xs[j]);
            hp[j] = hh; lp[j] = f2bf(xs[j] - bf2f(hh));
        }
        *(ushort4*)&g_w_h[(size_t)i * 4] = h;
        *(ushort4*)&g_w_l[(size_t)i * 4] = l;
    } else if (blk < EBLK + WBLK + ZBLK) {
        __shared__ float tile[32][33];
        const int zi = blk - (EBLK + WBLK);
        const int t0 = (zi & 31) * 32;
        const int k0 = ((zi >> 5) & 15) * 32;
        const int b  = zi >> 9;
        const int tx = tid & 31;
        const int ty = tid >> 5;
#pragma unroll
        for (int i = 0; i < 4; i++)
            tile[ty + 8 * i][tx] = z[(size_t)b * CT + (size_t)(k0 + ty + 8 * i) * T_SZ + t0 + tx];
        __syncthreads();
#pragma unroll
        for (int i = 0; i < 4; i++) {
            int tl = ty + 8 * i;
            float x = tile[tx][tl];
            size_t o = (size_t)(b * T_SZ + t0 + tl) * E_DIM + k0 + tx;
            g_zf[o] = x;
            g_z8[o] = f2e4(x * SZ_Z);
        }
    } else {
        int i = (blk - (EBLK + WBLK + ZBLK)) * 256 + tid;
        g_cbnorm[i] = 0.f;
        g_bmin[i & (ROWS - 1)] = 0xFFFFFFFFu;
        if (i == 0) {
            bool is64 = ((ad[1] | ad[3] | ad[5] | ad[7]) == 0);
            for (int b = 0; b < B_SZ; b++) {
                int dom = is64 ? ad[2 * b] : ad[b];
                int lo, hi;
                if (dom == 0)      { lo = 0;    hi = 2048; }
                else if (dom == 1) { lo = 2048; hi = 4096; }
                else if (dom == 2) { lo = 4096; hi = 8192; }
                else               { lo = 0;    hi = 8192; }
                g_lo[b] = lo; g_hi[b] = hi;
            }
        }
    }
}

// ======== L2: codebook (3-term split bf16 MMA, exact) — fully unrolled pipeline ========
__global__ __launch_bounds__(256, 2) void k_codebook_mma(const float* __restrict__ bias) {
    extern __shared__ char dsm[];
    const unsigned smb = smem_u32(dsm);
    float* bias_s = (float*)dsm;

    const int tid = threadIdx.x;
    const int lane = tid & 31, wid = tid >> 5;
    const int g = lane >> 2, t = lane & 3;
    const int warpM = wid >> 2, warpN = wid & 3;
    const int bx = blockIdx.x, by = blockIdx.y;

    if (tid < 128) bias_s[tid] = bias[by * 128 + tid];

    const int lrow = tid >> 1, lpart = tid & 1;
    const size_t aG = (size_t)(bx * 128 + lrow) * E_DIM + lpart * 16;
    const size_t bG = (size_t)(by * 128 + lrow) * E_DIM + lpart * 16;
    const unsigned dOff = (unsigned)(lrow * PITCH + lpart * 16) * 2;
    const unsigned stD = smb + 4096 + dOff;

    const int arow = (lane < 16) ? lane : lane - 16;
    const int akadd = (lane < 16) ? 0 : 8;
    const int brow = (lane & 7) + ((lane >= 16) ? 8 : 0);
    const int bkadd = ((lane >> 3) & 1) * 8;
    const unsigned baseAh = smb + 4096 + (unsigned)((warpM * 64 + arow) * PITCH + akadd) * 2;
    const unsigned baseBh = smb + 4096 + 2 * ARR_BYTES +
                            (unsigned)((warpN * 32 + brow) * PITCH + bkadd) * 2;

    float acc[4][4][4];
#pragma unroll
    for (int i = 0; i < 4; i++)
#pragma unroll
        for (int j = 0; j < 4; j++)
#pragma unroll
            for (int q = 0; q < 4; q++) acc[i][j][q] = 0.f;

    {
        cp16(stD,                  g_e_h + aG);      cp16(stD + 16,                  g_e_h + aG + 8);
        cp16(stD + ARR_BYTES,      g_e_l + aG);      cp16(stD + ARR_BYTES + 16,      g_e_l + aG + 8);
        cp16(stD + 2 * ARR_BYTES,  g_w_h + bG);      cp16(stD + 2 * ARR_BYTES + 16,  g_w_h + bG + 8);
        cp16(stD + 3 * ARR_BYTES,  g_w_l + bG);      cp16(stD + 3 * ARR_BYTES + 16,  g_w_l + bG + 8);
    }
    CP_COMMIT();

#pragma unroll
    for (int kc = 0; kc < 16; kc++) {
        const unsigned sOff = (kc & 1) * CB_STAGE;
        CP_WAIT0();
        __syncthreads();
        if (kc + 1 < 16) {
            const int kk = (kc + 1) * 32;
            const unsigned st = stD + ((kc + 1) & 1) * CB_STAGE;
            cp16(st,                  g_e_h + aG + kk);      cp16(st + 16,                  g_e_h + aG + kk + 8);
            cp16(st + ARR_BYTES,      g_e_l + aG + kk);      cp16(st + ARR_BYTES + 16,      g_e_l + aG + kk + 8);
            cp16(st + 2 * ARR_BYTES,  g_w_h + bG + kk);      cp16(st + 2 * ARR_BYTES + 16,  g_w_h + bG + kk + 8);
            cp16(st + 3 * ARR_BYTES,  g_w_l + bG + kk);      cp16(st + 3 * ARR_BYTES + 16,  g_w_l + bG + kk + 8);
        }
        CP_COMMIT();

#pragma unroll
        for (int ks = 0; ks < 2; ks++) {
            const unsigned kofs = ks * 32;
            unsigned bh[2][4], bl[2][4];
#pragma unroll
            for (int p = 0; p < 2; p++) {
                const unsigned ba = sOff + kofs + p * (16 * PITCH * 2);
                ldsm4(bh[p], baseBh + ba);
                ldsm4(bl[p], baseBh + ARR_BYTES + ba);
            }
#pragma unroll
            for (int mt = 0; mt < 4; mt++) {
                const unsigned aa = sOff + kofs + mt * (16 * PITCH * 2);
                unsigned ah[4], al[4];
                ldsm4(ah, baseAh + aa);
                ldsm4(al, baseAh + ARR_BYTES + aa);
#pragma unroll
                for (int nt = 0; nt < 4; nt++) {
                    const unsigned* bhp = &bh[nt >> 1][(nt & 1) * 2];
                    const unsigned* blp = &bl[nt >> 1][(nt & 1) * 2];
                    mma_bf16(acc[mt][nt], ah, bhp);
                    mma_bf16(acc[mt][nt], ah, blp);
                    mma_bf16(acc[mt][nt], al, bhp);
                }
            }
        }
    }

#pragma unroll
    for (int mt = 0; mt < 4; mt++) {
        float nrm0 = 0.f, nrm1 = 0.f;
#pragma unroll
        for (int nt = 0; nt < 4; nt++) {
            const int lcol = warpN * 32 + nt * 8 + 2 * t;
            const float b0 = bias_s[lcol], b1 = bias_s[lcol + 1];
            const int gc = by * 128 + lcol;
            const int r0 = bx * 128 + warpM * 64 + mt * 16 + g;
            float v0 = acc[mt][nt][0] + b0, v1 = acc[mt][nt][1] + b1;
            float v2 = acc[mt][nt][2] + b0, v3 = acc[mt][nt][3] + b1;
            size_t o0 = (size_t)r0 * E_DIM + gc;
            size_t o1 = (size_t)(r0 + 8) * E_DIM + gc;
            g_codebook[o0] = v0;         g_codebook[o0 + 1] = v1;
            g_codebook[o1] = v2;         g_codebook[o1 + 1] = v3;
            g_cb8[o0] = f2e4(v0 * SZ_CB); g_cb8[o0 + 1] = f2e4(v1 * SZ_CB);
            g_cb8[o1] = f2e4(v2 * SZ_CB); g_cb8[o1 + 1] = f2e4(v3 * SZ_CB);
            nrm0 += v0 * v0 + v1 * v1;
            nrm1 += v2 * v2 + v3 * v3;
        }
        nrm0 += __shfl_xor_sync(0xffffffffu, nrm0, 1);
        nrm0 += __shfl_xor_sync(0xffffffffu, nrm0, 2);
        nrm1 += __shfl_xor_sync(0xffffffffu, nrm1, 1);
        nrm1 += __shfl_xor_sync(0xffffffffu, nrm1, 2);
        if (t == 0) {
            const int r0 = bx * 128 + warpM * 64 + mt * 16 + g;
            atomicAdd(&g_cbnorm[r0], nrm0);
            atomicAdd(&g_cbnorm[r0 + 8], nrm1);
        }
    }
}

// ======== L3: fp8 screen — A resident, B quarter-local 2-stage, named barriers ========
__global__ __launch_bounds__(256, 2) void k_argmin_fp8() {
    extern __shared__ char dsm[];
    const unsigned smb = smem_u32(dsm);

    const int tid = threadIdx.x;
    const int lane = tid & 31, wid = tid >> 5;
    const int g = lane >> 2, t = lane & 3;
    const int warpM = wid >> 2, warpN = wid & 3;
    const int bx = blockIdx.x;
    const int b  = bx >> 3;
    const int c0 = blockIdx.y * 1024;
    if (c0 >= g_hi[b] || c0 + 1024 <= g_lo[b]) return;

    const int lrow = tid >> 1, lpart = tid & 1;
    const size_t aG = (size_t)(bx * 128 + lrow) * E_DIM + lpart * 32;
    const unsigned baseDA = smb + (unsigned)(lrow * 80 + lpart * 32);

    const int qbar = warpN + 1;
    const int qtid = ((wid >= 4) ? 32 : 0) + lane;
    const int brow_ld = warpN * 32 + (qtid >> 1);
    const int bhalf = qtid & 1;
    const size_t bGq = (size_t)(c0 + brow_ld) * E_DIM + bhalf * 32;
    const unsigned baseDB = smb + B_BASE + (unsigned)(brow_ld * 80 + bhalf * 32);

    const int arow = (lane < 16) ? lane : lane - 16;
    const int akadd = (lane < 16) ? 0 : 16;
    const int brow = (lane & 7) + ((lane >= 16) ? 8 : 0);
    const int bkadd = ((lane >> 3) & 1) * 16;
    const unsigned baseA = smb + (unsigned)((warpM * 64 + arow) * 80 + akadd);
    const unsigned baseB = smb + B_BASE + (unsigned)((warpN * 32 + brow) * 80 + bkadd);

    unsigned short* const sOut =
        g_scores + (size_t)(bx * 128 + warpM * 64 + g) * N_E + (c0 + warpN * 32 + 2 * t);
    const int colT = c0 + warpN * 32 + 2 * t;

    float acc[4][4][4];
#pragma unroll
    for (int i = 0; i < 4; i++)
#pragma unroll
        for (int j = 0; j < 4; j++)
#pragma unroll
            for (int q = 0; q < 4; q++) acc[i][j][q] = 0.f;

    float bestS[4][2];
#pragma unroll
    for (int i = 0; i < 4; i++) { bestS[i][0] = 3.4e38f; bestS[i][1] = 3.4e38f; }

#pragma unroll
    for (int c = 0; c < 8; c++) {
        cp16(baseDA + c * A_CHUNK,      g_z8 + aG + c * 64);
        cp16(baseDA + c * A_CHUNK + 16, g_z8 + aG + c * 64 + 16);
    }
    cp16(baseDB,      g_cb8 + bGq);
    cp16(baseDB + 16, g_cb8 + bGq + 16);
    CP_COMMIT();
    CP_WAIT0();
    __syncthreads();

    for (int it8 = 0; it8 < 64; it8 += 8) {
        const size_t bRow = bGq + (size_t)((it8 >> 3) * 128) * E_DIM;
        const size_t bRowN = bRow + (size_t)128 * E_DIM;
#pragma unroll
        for (int u = 0; u < 8; u++) {
            if (it8 + u > 0) {
                CP_WAIT0();
                BARQ(qbar);
            }
            if (it8 + u + 1 < 64) {
                const unsigned st = baseDB + (((u + 1) & 1)) * A_CHUNK;
                const int kk = ((u + 1) & 7) * 64;
                const size_t bS = (u == 7 ? bRowN : bRow) + kk;
                cp16(st,      g_cb8 + bS);
                cp16(st + 16, g_cb8 + bS + 16);
            }
            CP_COMMIT();

            const unsigned stgB = (u & 1) * A_CHUNK;
            const unsigned stgA = u * A_CHUNK;
#pragma unroll
            for (int ks = 0; ks < 2; ks++) {
                const int kofs = ks * 32;
                unsigned bh[2][4];
                ldsm4(bh[0], baseB + stgB + kofs);
                ldsm4(bh[1], baseB + stgB + 1280 + kofs);
#pragma unroll
                for (int mt = 0; mt < 4; mt++) {
                    unsigned ah[4];
                    ldsm4(ah, baseA + stgA + mt * 1280 + kofs);
#pragma unroll
                    for (int nt = 0; nt < 4; nt++)
                        mma_fp8(acc[mt][nt], ah, &bh[nt >> 1][(nt & 1) * 2]);
                }
            }

            if (u == 7) {
                const int ngOff = (it8 >> 3) * 128;
                float cn0[4], cn1[4];
#pragma unroll
                for (int nt = 0; nt < 4; nt++) {
                    cn0[nt] = __ldg(&g_cbnorm[colT + ngOff + nt * 8]);
                    cn1[nt] = __ldg(&g_cbnorm[colT + ngOff + nt * 8 + 1]);
                }
#pragma unroll
                for (int mt = 0; mt < 4; mt++) {
                    unsigned short* r0p = sOut + (size_t)(mt * 16) * N_E + ngOff;
                    unsigned short* r1p = r0p + (size_t)8 * N_E;
                    float m0 = bestS[mt][0], m1 = bestS[mt][1];
#pragma unroll
                    for (int nt = 0; nt < 4; nt++) {
                        float s0 = fmaf(NEG2INV, acc[mt][nt][0], cn0[nt]);
                        float s1 = fmaf(NEG2INV, acc[mt][nt][1], cn1[nt]);
                        float s2 = fmaf(NEG2INV, acc[mt][nt][2], cn0[nt]);
                        float s3 = fmaf(NEG2INV, acc[mt][nt][3], cn1[nt]);
                        m0 = fminf(m0, fminf(s0, s1));
                        m1 = fminf(m1, fminf(s2, s3));
                        ushort2 p01 = {f2bf(acc[mt][nt][0]), f2bf(acc[mt][nt][1])};
                        ushort2 p23 = {f2bf(acc[mt][nt][2]), f2bf(acc[mt][nt][3])};
                        *(ushort2*)(r0p + nt * 8) = p01;
                        *(ushort2*)(r1p + nt * 8) = p23;
                        acc[mt][nt][0] = 0.f; acc[mt][nt][1] = 0.f;
                        acc[mt][nt][2] = 0.f; acc[mt][nt][3] = 0.f;
                    }
                    bestS[mt][0] = m0; bestS[mt][1] = m1;
                }
            }
        }
    }

#pragma unroll
    for (int mt = 0; mt < 4; mt++)
#pragma unroll
        for (int h = 0; h < 2; h++) {
            float m = bestS[mt][h];
            m = fminf(m, __shfl_xor_sync(0xffffffffu, m, 1));
            m = fminf(m, __shfl_xor_sync(0xffffffffu, m, 2));
            if (t == 0)
                atomicMin(&g_bmin[bx * 128 + warpM * 64 + mt * 16 + h * 8 + g], fkey(m));
        }
}

// ======== L4: scan — 4 rows/block, quarter-local collect + rescore ========
__global__ __launch_bounds__(256) void k_scan() {
    __shared__ int   scnt[4];
    __shared__ int   cand[4][256];
    __shared__ unsigned long long wbest[4][2];

    const int tid = threadIdx.x;
    const int q   = tid >> 6;            // quarter 0..3
    const int qt  = tid & 63;            // thread within quarter
    const int row = blockIdx.x * 4 + q;
    const int b = row >> 10;
    const int lo = g_lo[b], hi = g_hi[b];

    const float thresh = fkey_inv(g_bmin[row]) + MARGIN;
    if (qt == 0) scnt[q] = 0;
    BARQ(q + 1);

    // collect: uint4 = 8 bf16 scores per thread per trip (8 trips)
    const uint4* srow4 = (const uint4*)(g_scores + (size_t)row * N_E);
    for (int j8 = (lo >> 3) + qt; j8 < (hi >> 3); j8 += 64) {
        uint4 v = srow4[j8];
        const int j0 = j8 << 3;
        float4 cnA = *(const float4*)&g_cbnorm[j0];
        float4 cnB = *(const float4*)&g_cbnorm[j0 + 4];
        unsigned w[4] = {v.x, v.y, v.z, v.w};
        float cn[8] = {cnA.x, cnA.y, cnA.z, cnA.w, cnB.x, cnB.y, cnB.z, cnB.w};
#pragma unroll
        for (int k = 0; k < 4; k++) {
            float dLo = __uint_as_float(w[k] << 16);
            float dHi = __uint_as_float(w[k] & 0xFFFF0000u);
            float sa = fmaf(NEG2INV, dLo, cn[2 * k]);
            float sb = fmaf(NEG2INV, dHi, cn[2 * k + 1]);
            if (sa <= thresh) {
                int pos = atomicAdd(&scnt[q], 1);
                if (pos < 256) cand[q][pos] = j0 + 2 * k;
            }
            if (sb <= thresh) {
                int pos = atomicAdd(&scnt[q], 1);
                if (pos < 256) cand[q][pos] = j0 + 2 * k + 1;
            }
        }
    }
    BARQ(q + 1);
    int nc = scnt[q] < 256 ? scnt[q] : 256;

    // exact fp32 rescore; 2 warps per quarter, warp per candidate
    const int lane = qt & 31, qw = qt >> 5;
    unsigned long long best = ~0ull;
    const float* zr = g_zf + (size_t)row * E_DIM;
    for (int ci = qw; ci < nc; ci += 2) {
        const int j = cand[q][ci];
        const float* cbr = g_codebook + (size_t)j * E_DIM;
        float dot = 0.f;
#pragma unroll
        for (int d = lane; d < E_DIM; d += 32)
            dot = fmaf(zr[d], cbr[d], dot);
#pragma unroll
        for (int o = 16; o; o >>= 1) dot += __shfl_xor_sync(0xffffffffu, dot, o);
        float s = fmaf(-2.f, dot, g_cbnorm[j]);
        unsigned long long key = ((unsigned long long)fkey(s) << 32) | (unsigned)j;
        if (key < best) best = key;
    }
    if (lane == 0) wbest[q][qw] = best;
    BARQ(q + 1);
    if (qt == 0) {
        unsigned long long k = wbest[q][0];
        if (wbest[q][1] < k) k = wbest[q][1];
        g_best[row] = k;
    }
}

// ======== L5: gather z_q, write min_idx, loss partials ========
__global__ __launch_bounds__(256) void k_gather(const float* __restrict__ z,
                                                float* __restrict__ out) {
    __shared__ int sidx[32];
    __shared__ float sred[256];
    const int blk = blockIdx.x;
    const int r0  = blk * 32;
    const int b   = r0 >> 10;
    const int t0  = r0 & 1023;
    const int tid = threadIdx.x;

    if (tid < 32) {
        unsigned long long key = g_best[r0 + tid];
        int idx = (int)(key & 0xffffffffull);
        sidx[tid] = idx;
        out[ZQ_ELEMS + r0 + tid] = (float)idx;
    }
    __syncthreads();

    const int t  = tid & 31;
    const int dl = tid >> 5;
    const int row = sidx[t];
    const float* cbr = g_codebook + (size_t)row * E_DIM;
    const size_t obase = (size_t)b * CT + t0 + t;
    float lacc = 0.f;
#pragma unroll 8
    for (int d = dl; d < E_DIM; d += 8) {
        float v  = cbr[d];
        float zt = z[obase + (size_t)d * T_SZ];
        float df = v - zt;
        lacc += df * df;
        out[obase + (size_t)d * T_SZ] = v;
    }
    sred[tid] = lacc;
    __syncthreads();
#pragma unroll
    for (int o = 128; o; o >>= 1) {
        if (tid < o) sred[tid] += sred[tid + o];
        __syncthreads();
    }
    if (tid == 0) g_partial[blk] = sred[0];
}

// ======== L6: finalize loss ========
__global__ void k_final(float* __restrict__ out) {
    __shared__ float sr[256];
    int tid = threadIdx.x;
    sr[tid] = g_partial[tid];
    __syncthreads();
#pragma unroll
    for (int o = 128; o; o >>= 1) {
        if (tid < o) sr[tid] += sr[tid + o];
        __syncthreads();
    }
    if (tid == 0)
        out[ZQ_ELEMS + ROWS] = sr[0] * 1.25f / (float)ZQ_ELEMS;
}

extern "C" void kernel_launch(void* const* d_in, const int* in_sizes, int n_in,
                              void* d_out, int out_size) {
    int i_z = -1, i_emb = -1, i_ad = -1, i_pw = -1, i_pb = -1;
    for (int i = 0; i < n_in; i++) {
        int s = in_sizes[i];
        if (s == ZQ_ELEMS) { if (i_z < 0) i_z = i; else i_emb = i; }
        else if (s == E_DIM * E_DIM) i_pw = i;
        else if (s == E_DIM)         i_pb = i;
        else if (s == B_SZ)          i_ad = i;
    }
    const float* z   = (const float*)d_in[i_z];
    const int*   ad  = (const int*)d_in[i_ad];
    const float* emb = (const float*)d_in[i_emb];
    const float* pw  = (const float*)d_in[i_pw];
    const float* pb  = (const float*)d_in[i_pb];
    float* out = (float*)d_out;

    cudaFuncSetAttribute(k_codebook_mma, cudaFuncAttributeMaxDynamicSharedMemorySize, SMEM_CB);
    cudaFuncSetAttribute(k_argmin_fp8,   cudaFuncAttributeMaxDynamicSharedMemorySize, SMEM_AG);

    k_split_all<<<EBLK + WBLK + ZBLK + SBLK, 256>>>(emb, pw, z, ad);        // 1
    k_codebook_mma<<<dim3(N_E / 128, E_DIM / 128), 256, SMEM_CB>>>(pb);     // 2
    k_argmin_fp8<<<dim3(64, 8), 256, SMEM_AG>>>();                          // 3
    k_scan<<<ROWS / 4, 256>>>();                                            // 4 (profiled)
    k_gather<<<ROWS / 32, 256>>>(z, out);                                   // 5
    k_final<<<1, 256>>>(out);                                               // 6
}

// round 16
// speedup vs baseline: 1.0753x; 1.0753x over previous
#include <cuda_runtime.h>

#define N_E   8192
#define E_DIM 512
#define B_SZ  8
#define T_SZ  1024
#define ROWS  (B_SZ * T_SZ)
#define CT    (E_DIM * T_SZ)
#define ZQ_ELEMS (B_SZ * E_DIM * T_SZ)

#define PITCH 40                         // halves per SMEM row (bf16 codebook kernel)
#define ARR_BYTES   10240
#define MARGIN 1.0f
#define SZ_Z  16.0f
#define SZ_CB 1024.0f
#define NEG2INV (-1.220703125e-4f)       // -2/(16*1024)

#define CB_STAGE (4 * ARR_BYTES)
#define SMEM_CB  (4096 + 2 * CB_STAGE)

// fp8 screen: A resident (8 chunks x 128 rows x 80B), B 2-stage
#define A_CHUNK 10240
#define B_BASE  (8 * A_CHUNK)            // 81920
#define SMEM_AG (B_BASE + 2 * A_CHUNK)   // 102400

// -------- scratch --------
__device__ float g_codebook[N_E * E_DIM];
__device__ float g_cbnorm[N_E];
__device__ float g_zf[ROWS * E_DIM];
__device__ unsigned char g_cb8[N_E * E_DIM];       // e4m3, scale 1024
__device__ unsigned char g_z8[ROWS * E_DIM];       // e4m3, scale 16
__device__ unsigned short g_e_h[N_E * E_DIM];
__device__ unsigned short g_e_l[N_E * E_DIM];
__device__ unsigned short g_w_h[E_DIM * E_DIM];
__device__ unsigned short g_w_l[E_DIM * E_DIM];
__device__ unsigned short g_scores[(size_t)ROWS * N_E];  // bf16 raw scaled dots
__device__ unsigned g_bmin[ROWS];                  // fkey(min screen score)
__device__ unsigned long long g_best[ROWS];
__device__ float g_partial[ROWS / 32];
__device__ int g_lo[B_SZ], g_hi[B_SZ];

__device__ __forceinline__ unsigned int fkey(float f) {
    unsigned int u = __float_as_uint(f);
    return (u & 0x80000000u) ? ~u : (u | 0x80000000u);
}
__device__ __forceinline__ float fkey_inv(unsigned u) {
    return __uint_as_float((u & 0x80000000u) ? (u ^ 0x80000000u) : ~u);
}
__device__ __forceinline__ unsigned short f2bf(float x) {
    unsigned u = __float_as_uint(x);
    unsigned rb = 0x7FFFu + ((u >> 16) & 1u);
    return (unsigned short)((u + rb) >> 16);
}
__device__ __forceinline__ float bf2f(unsigned short h) {
    return __uint_as_float(((unsigned)h) << 16);
}
__device__ __forceinline__ unsigned char f2e4(float x) {
    unsigned short v;
    asm("cvt.rn.satfinite.e4m3x2.f32 %0, %1, %1;" : "=h"(v) : "f"(x));
    return (unsigned char)(v & 0xFF);
}
__device__ __forceinline__ unsigned smem_u32(const void* p) {
    unsigned a;
    asm("{ .reg .u64 t; cvta.to.shared.u64 t, %1; cvt.u32.u64 %0, t; }" : "=r"(a) : "l"(p));
    return a;
}
__device__ __forceinline__ void mma_bf16(float* c, const unsigned* a, const unsigned* b) {
    asm volatile(
        "mma.sync.aligned.m16n8k16.row.col.f32.bf16.bf16.f32 "
        "{%0,%1,%2,%3}, {%4,%5,%6,%7}, {%8,%9}, {%0,%1,%2,%3};"
        : "+f"(c[0]), "+f"(c[1]), "+f"(c[2]), "+f"(c[3])
        : "r"(a[0]), "r"(a[1]), "r"(a[2]), "r"(a[3]), "r"(b[0]), "r"(b[1]));
}
__device__ __forceinline__ void mma_fp8(float* c, const unsigned* a, const unsigned* b) {
    asm volatile(
        "mma.sync.aligned.m16n8k32.row.col.f32.e4m3.e4m3.f32 "
        "{%0,%1,%2,%3}, {%4,%5,%6,%7}, {%8,%9}, {%0,%1,%2,%3};"
        : "+f"(c[0]), "+f"(c[1]), "+f"(c[2]), "+f"(c[3])
        : "r"(a[0]), "r"(a[1]), "r"(a[2]), "r"(a[3]), "r"(b[0]), "r"(b[1]));
}
__device__ __forceinline__ void ldsm4(unsigned* r, unsigned addr) {
    asm volatile("ldmatrix.sync.aligned.m8n8.x4.shared.b16 {%0,%1,%2,%3}, [%4];"
                 : "=r"(r[0]), "=r"(r[1]), "=r"(r[2]), "=r"(r[3]) : "r"(addr));
}
__device__ __forceinline__ void cp16(unsigned dst, const void* src) {
    asm volatile("cp.async.cg.shared.global [%0], [%1], 16;" :: "r"(dst), "l"(src));
}
#define CP_COMMIT() asm volatile("cp.async.commit_group;" ::: "memory")
#define CP_WAIT0()  asm volatile("cp.async.wait_group 0;" ::: "memory")
#define BARQ(id) asm volatile("bar.sync %0, 64;" :: "r"(id) : "memory")

// ======== L1: fused splits + setup ========
#define EBLK (N_E * E_DIM / 4 / 256)     // 4096
#define WBLK (E_DIM * E_DIM / 4 / 256)   // 256
#define ZBLK 4096
#define SBLK (N_E / 256)                 // 32 (setup blocks)
__global__ __launch_bounds__(256) void k_split_all(const float* __restrict__ emb,
                                                   const float* __restrict__ pw,
                                                   const float* __restrict__ z,
                                                   const int* __restrict__ ad) {
    const int blk = blockIdx.x;
    const int tid = threadIdx.x;
    if (blk < EBLK) {
        int i = blk * 256 + tid;
        float4 v = ((const float4*)emb)[i];
        float xs[4] = {v.x, v.y, v.z, v.w};
        ushort4 h, l;
        unsigned short* hp = &h.x; unsigned short* lp = &l.x;
#pragma unroll
        for (int j = 0; j < 4; j++) {
            unsigned short hh = f2bf(xs[j]);
            hp[j] = hh; lp[j] = f2bf(xs[j] - bf2f(hh));
        }
        *(ushort4*)&g_e_h[(size_t)i * 4] = h;
        *(ushort4*)&g_e_l[(size_t)i * 4] = l;
    } else if (blk < EBLK + WBLK) {
        int i = (blk - EBLK) * 256 + tid;
        float4 v = ((const float4*)pw)[i];
        float xs[4] = {v.x, v.y, v.z, v.w};
        ushort4 h, l;
        unsigned short* hp = &h.x; unsigned short* lp = &l.x;
#pragma unroll
        for (int j = 0; j < 4; j++) {
            unsigned short hh = f2bf(xs[j]);
            hp[j] = hh; lp[j] = f2bf(xs[j] - bf2f(hh));
        }
        *(ushort4*)&g_w_h[(size_t)i * 4] = h;
        *(ushort4*)&g_w_l[(size_t)i * 4] = l;
    } else if (blk < EBLK + WBLK + ZBLK) {
        __shared__ float tile[32][33];
        const int zi = blk - (EBLK + WBLK);
        const int t0 = (zi & 31) * 32;
        const int k0 = ((zi >> 5) & 15) * 32;
        const int b  = zi >> 9;
        const int tx = tid & 31;
        const int ty = tid >> 5;
#pragma unroll
        for (int i = 0; i < 4; i++)
            tile[ty + 8 * i][tx] = z[(size_t)b * CT + (size_t)(k0 + ty + 8 * i) * T_SZ + t0 + tx];
        __syncthreads();
#pragma unroll
        for (int i = 0; i < 4; i++) {
            int tl = ty + 8 * i;
            float x = tile[tx][tl];
            size_t o = (size_t)(b * T_SZ + t0 + tl) * E_DIM + k0 + tx;
            g_zf[o] = x;
            g_z8[o] = f2e4(x * SZ_Z);
        }
    } else {
        int i = (blk - (EBLK + WBLK + ZBLK)) * 256 + tid;
        g_cbnorm[i] = 0.f;
        g_bmin[i & (ROWS - 1)] = 0xFFFFFFFFu;
        if (i == 0) {
            bool is64 = ((ad[1] | ad[3] | ad[5] | ad[7]) == 0);
            for (int b = 0; b < B_SZ; b++) {
                int dom = is64 ? ad[2 * b] : ad[b];
                int lo, hi;
                if (dom == 0)      { lo = 0;    hi = 2048; }
                else if (dom == 1) { lo = 2048; hi = 4096; }
                else if (dom == 2) { lo = 4096; hi = 8192; }
                else               { lo = 0;    hi = 8192; }
                g_lo[b] = lo; g_hi[b] = hi;
            }
        }
    }
}

// ======== L2: codebook (3-term split bf16 MMA, exact) — fully unrolled pipeline ========
__global__ __launch_bounds__(256, 2) void k_codebook_mma(const float* __restrict__ bias) {
    extern __shared__ char dsm[];
    const unsigned smb = smem_u32(dsm);
    float* bias_s = (float*)dsm;

    const int tid = threadIdx.x;
    const int lane = tid & 31, wid = tid >> 5;
    const int g = lane >> 2, t = lane & 3;
    const int warpM = wid >> 2, warpN = wid & 3;
    const int bx = blockIdx.x, by = blockIdx.y;

    if (tid < 128) bias_s[tid] = bias[by * 128 + tid];

    const int lrow = tid >> 1, lpart = tid & 1;
    const size_t aG = (size_t)(bx * 128 + lrow) * E_DIM + lpart * 16;
    const size_t bG = (size_t)(by * 128 + lrow) * E_DIM + lpart * 16;
    const unsigned dOff = (unsigned)(lrow * PITCH + lpart * 16) * 2;
    const unsigned stD = smb + 4096 + dOff;

    const int arow = (lane < 16) ? lane : lane - 16;
    const int akadd = (lane < 16) ? 0 : 8;
    const int brow = (lane & 7) + ((lane >= 16) ? 8 : 0);
    const int bkadd = ((lane >> 3) & 1) * 8;
    const unsigned baseAh = smb + 4096 + (unsigned)((warpM * 64 + arow) * PITCH + akadd) * 2;
    const unsigned baseBh = smb + 4096 + 2 * ARR_BYTES +
                            (unsigned)((warpN * 32 + brow) * PITCH + bkadd) * 2;

    float acc[4][4][4];
#pragma unroll
    for (int i = 0; i < 4; i++)
#pragma unroll
        for (int j = 0; j < 4; j++)
#pragma unroll
            for (int q = 0; q < 4; q++) acc[i][j][q] = 0.f;

    {
        cp16(stD,                  g_e_h + aG);      cp16(stD + 16,                  g_e_h + aG + 8);
        cp16(stD + ARR_BYTES,      g_e_l + aG);      cp16(stD + ARR_BYTES + 16,      g_e_l + aG + 8);
        cp16(stD + 2 * ARR_BYTES,  g_w_h + bG);      cp16(stD + 2 * ARR_BYTES + 16,  g_w_h + bG + 8);
        cp16(stD + 3 * ARR_BYTES,  g_w_l + bG);      cp16(stD + 3 * ARR_BYTES + 16,  g_w_l + bG + 8);
    }
    CP_COMMIT();

#pragma unroll
    for (int kc = 0; kc < 16; kc++) {
        const unsigned sOff = (kc & 1) * CB_STAGE;
        CP_WAIT0();
        __syncthreads();
        if (kc + 1 < 16) {
            const int kk = (kc + 1) * 32;
            const unsigned st = stD + ((kc + 1) & 1) * CB_STAGE;
            cp16(st,                  g_e_h + aG + kk);      cp16(st + 16,                  g_e_h + aG + kk + 8);
            cp16(st + ARR_BYTES,      g_e_l + aG + kk);      cp16(st + ARR_BYTES + 16,      g_e_l + aG + kk + 8);
            cp16(st + 2 * ARR_BYTES,  g_w_h + bG + kk);      cp16(st + 2 * ARR_BYTES + 16,  g_w_h + bG + kk + 8);
            cp16(st + 3 * ARR_BYTES,  g_w_l + bG + kk);      cp16(st + 3 * ARR_BYTES + 16,  g_w_l + bG + kk + 8);
        }
        CP_COMMIT();

#pragma unroll
        for (int ks = 0; ks < 2; ks++) {
            const unsigned kofs = ks * 32;
            unsigned bh[2][4], bl[2][4];
#pragma unroll
            for (int p = 0; p < 2; p++) {
                const unsigned ba = sOff + kofs + p * (16 * PITCH * 2);
                ldsm4(bh[p], baseBh + ba);
                ldsm4(bl[p], baseBh + ARR_BYTES + ba);
            }
#pragma unroll
            for (int mt = 0; mt < 4; mt++) {
                const unsigned aa = sOff + kofs + mt * (16 * PITCH * 2);
                unsigned ah[4], al[4];
                ldsm4(ah, baseAh + aa);
                ldsm4(al, baseAh + ARR_BYTES + aa);
#pragma unroll
                for (int nt = 0; nt < 4; nt++) {
                    const unsigned* bhp = &bh[nt >> 1][(nt & 1) * 2];
                    const unsigned* blp = &bl[nt >> 1][(nt & 1) * 2];
                    mma_bf16(acc[mt][nt], ah, bhp);
                    mma_bf16(acc[mt][nt], ah, blp);
                    mma_bf16(acc[mt][nt], al, bhp);
                }
            }
        }
    }

#pragma unroll
    for (int mt = 0; mt < 4; mt++) {
        float nrm0 = 0.f, nrm1 = 0.f;
#pragma unroll
        for (int nt = 0; nt < 4; nt++) {
            const int lcol = warpN * 32 + nt * 8 + 2 * t;
            const float b0 = bias_s[lcol], b1 = bias_s[lcol + 1];
            const int gc = by * 128 + lcol;
            const int r0 = bx * 128 + warpM * 64 + mt * 16 + g;
            float v0 = acc[mt][nt][0] + b0, v1 = acc[mt][nt][1] + b1;
            float v2 = acc[mt][nt][2] + b0, v3 = acc[mt][nt][3] + b1;
            size_t o0 = (size_t)r0 * E_DIM + gc;
            size_t o1 = (size_t)(r0 + 8) * E_DIM + gc;
            g_codebook[o0] = v0;         g_codebook[o0 + 1] = v1;
            g_codebook[o1] = v2;         g_codebook[o1 + 1] = v3;
            g_cb8[o0] = f2e4(v0 * SZ_CB); g_cb8[o0 + 1] = f2e4(v1 * SZ_CB);
            g_cb8[o1] = f2e4(v2 * SZ_CB); g_cb8[o1 + 1] = f2e4(v3 * SZ_CB);
            nrm0 += v0 * v0 + v1 * v1;
            nrm1 += v2 * v2 + v3 * v3;
        }
        nrm0 += __shfl_xor_sync(0xffffffffu, nrm0, 1);
        nrm0 += __shfl_xor_sync(0xffffffffu, nrm0, 2);
        nrm1 += __shfl_xor_sync(0xffffffffu, nrm1, 1);
        nrm1 += __shfl_xor_sync(0xffffffffu, nrm1, 2);
        if (t == 0) {
            const int r0 = bx * 128 + warpM * 64 + mt * 16 + g;
            atomicAdd(&g_cbnorm[r0], nrm0);
            atomicAdd(&g_cbnorm[r0 + 8], nrm1);
        }
    }
}

// ======== L3: fp8 screen — A resident, B quarter-local 2-stage, named barriers ========
__global__ __launch_bounds__(256, 2) void k_argmin_fp8() {
    extern __shared__ char dsm[];
    const unsigned smb = smem_u32(dsm);

    const int tid = threadIdx.x;
    const int lane = tid & 31, wid = tid >> 5;
    const int g = lane >> 2, t = lane & 3;
    const int warpM = wid >> 2, warpN = wid & 3;
    const int bx = blockIdx.x;
    const int b  = bx >> 3;
    const int c0 = blockIdx.y * 1024;
    if (c0 >= g_hi[b] || c0 + 1024 <= g_lo[b]) return;

    const int lrow = tid >> 1, lpart = tid & 1;
    const size_t aG = (size_t)(bx * 128 + lrow) * E_DIM + lpart * 32;
    const unsigned baseDA = smb + (unsigned)(lrow * 80 + lpart * 32);

    const int qbar = warpN + 1;
    const int qtid = ((wid >= 4) ? 32 : 0) + lane;
    const int brow_ld = warpN * 32 + (qtid >> 1);
    const int bhalf = qtid & 1;
    const size_t bGq = (size_t)(c0 + brow_ld) * E_DIM + bhalf * 32;
    const unsigned baseDB = smb + B_BASE + (unsigned)(brow_ld * 80 + bhalf * 32);

    const int arow = (lane < 16) ? lane : lane - 16;
    const int akadd = (lane < 16) ? 0 : 16;
    const int brow = (lane & 7) + ((lane >= 16) ? 8 : 0);
    const int bkadd = ((lane >> 3) & 1) * 16;
    const unsigned baseA = smb + (unsigned)((warpM * 64 + arow) * 80 + akadd);
    const unsigned baseB = smb + B_BASE + (unsigned)((warpN * 32 + brow) * 80 + bkadd);

    unsigned short* const sOut =
        g_scores + (size_t)(bx * 128 + warpM * 64 + g) * N_E + (c0 + warpN * 32 + 2 * t);
    const int colT = c0 + warpN * 32 + 2 * t;

    float acc[4][4][4];
#pragma unroll
    for (int i = 0; i < 4; i++)
#pragma unroll
        for (int j = 0; j < 4; j++)
#pragma unroll
            for (int q = 0; q < 4; q++) acc[i][j][q] = 0.f;

    float bestS[4][2];
#pragma unroll
    for (int i = 0; i < 4; i++) { bestS[i][0] = 3.4e38f; bestS[i][1] = 3.4e38f; }

#pragma unroll
    for (int c = 0; c < 8; c++) {
        cp16(baseDA + c * A_CHUNK,      g_z8 + aG + c * 64);
        cp16(baseDA + c * A_CHUNK + 16, g_z8 + aG + c * 64 + 16);
    }
    cp16(baseDB,      g_cb8 + bGq);
    cp16(baseDB + 16, g_cb8 + bGq + 16);
    CP_COMMIT();
    CP_WAIT0();
    __syncthreads();

    for (int it8 = 0; it8 < 64; it8 += 8) {
        const size_t bRow = bGq + (size_t)((it8 >> 3) * 128) * E_DIM;
        const size_t bRowN = bRow + (size_t)128 * E_DIM;
#pragma unroll
        for (int u = 0; u < 8; u++) {
            if (it8 + u > 0) {
                CP_WAIT0();
                BARQ(qbar);
            }
            if (it8 + u + 1 < 64) {
                const unsigned st = baseDB + (((u + 1) & 1)) * A_CHUNK;
                const int kk = ((u + 1) & 7) * 64;
                const size_t bS = (u == 7 ? bRowN : bRow) + kk;
                cp16(st,      g_cb8 + bS);
                cp16(st + 16, g_cb8 + bS + 16);
            }
            CP_COMMIT();

            const unsigned stgB = (u & 1) * A_CHUNK;
            const unsigned stgA = u * A_CHUNK;
#pragma unroll
            for (int ks = 0; ks < 2; ks++) {
                const int kofs = ks * 32;
                unsigned bh[2][4];
                ldsm4(bh[0], baseB + stgB + kofs);
                ldsm4(bh[1], baseB + stgB + 1280 + kofs);
#pragma unroll
                for (int mt = 0; mt < 4; mt++) {
                    unsigned ah[4];
                    ldsm4(ah, baseA + stgA + mt * 1280 + kofs);
#pragma unroll
                    for (int nt = 0; nt < 4; nt++)
                        mma_fp8(acc[mt][nt], ah, &bh[nt >> 1][(nt & 1) * 2]);
                }
            }

            if (u == 7) {
                const int ngOff = (it8 >> 3) * 128;
                float cn0[4], cn1[4];
#pragma unroll
                for (int nt = 0; nt < 4; nt++) {
                    cn0[nt] = __ldg(&g_cbnorm[colT + ngOff + nt * 8]);
                    cn1[nt] = __ldg(&g_cbnorm[colT + ngOff + nt * 8 + 1]);
                }
#pragma unroll
                for (int mt = 0; mt < 4; mt++) {
                    unsigned short* r0p = sOut + (size_t)(mt * 16) * N_E + ngOff;
                    unsigned short* r1p = r0p + (size_t)8 * N_E;
                    float m0 = bestS[mt][0], m1 = bestS[mt][1];
#pragma unroll
                    for (int nt = 0; nt < 4; nt++) {
                        float s0 = fmaf(NEG2INV, acc[mt][nt][0], cn0[nt]);
                        float s1 = fmaf(NEG2INV, acc[mt][nt][1], cn1[nt]);
                        float s2 = fmaf(NEG2INV, acc[mt][nt][2], cn0[nt]);
                        float s3 = fmaf(NEG2INV, acc[mt][nt][3], cn1[nt]);
                        m0 = fminf(m0, fminf(s0, s1));
                        m1 = fminf(m1, fminf(s2, s3));
                        ushort2 p01 = {f2bf(acc[mt][nt][0]), f2bf(acc[mt][nt][1])};
                        ushort2 p23 = {f2bf(acc[mt][nt][2]), f2bf(acc[mt][nt][3])};
                        *(ushort2*)(r0p + nt * 8) = p01;
                        *(ushort2*)(r1p + nt * 8) = p23;
                        acc[mt][nt][0] = 0.f; acc[mt][nt][1] = 0.f;
                        acc[mt][nt][2] = 0.f; acc[mt][nt][3] = 0.f;
                    }
                    bestS[mt][0] = m0; bestS[mt][1] = m1;
                }
            }
        }
    }

#pragma unroll
    for (int mt = 0; mt < 4; mt++)
#pragma unroll
        for (int h = 0; h < 2; h++) {
            float m = bestS[mt][h];
            m = fminf(m, __shfl_xor_sync(0xffffffffu, m, 1));
            m = fminf(m, __shfl_xor_sync(0xffffffffu, m, 2));
            if (t == 0)
                atomicMin(&g_bmin[bx * 128 + warpM * 64 + mt * 16 + h * 8 + g], fkey(m));
        }
}

// ======== L4: scan — 1 row/block, paired-load collect + exact fp32 rescore ========
__global__ __launch_bounds__(256) void k_scan() {
    __shared__ int   scnt;
    __shared__ int   cand[512];
    __shared__ unsigned long long wbest[8];

    const int row = blockIdx.x;
    const int tid = threadIdx.x;
    const int lane = tid & 31, wid = tid >> 5;
    const int b = row >> 10;
    const int lo = g_lo[b], hi = g_hi[b];

    const float thresh = fkey_inv(g_bmin[row]) + MARGIN;
    if (tid == 0) scnt = 0;
    __syncthreads();

    // collect: two paired uint4 loads (stride 256) per trip for MLP
    const uint4* srow4 = (const uint4*)(g_scores + (size_t)row * N_E);
    const int j8lo = lo >> 3, j8hi = hi >> 3;
    for (int j8 = j8lo + tid; j8 < j8hi; j8 += 512) {
        const int j8b = j8 + 256;
        const bool p2 = (j8b < j8hi);
        uint4 v0 = srow4[j8];
        uint4 v1 = p2 ? srow4[j8b] : make_uint4(0, 0, 0, 0);
        const int j00 = j8 << 3, j01 = j8b << 3;
        float4 cnA0 = *(const float4*)&g_cbnorm[j00];
        float4 cnB0 = *(const float4*)&g_cbnorm[j00 + 4];
        float4 cnA1 = p2 ? *(const float4*)&g_cbnorm[j01] : make_float4(0, 0, 0, 0);
        float4 cnB1 = p2 ? *(const float4*)&g_cbnorm[j01 + 4] : make_float4(0, 0, 0, 0);

        unsigned w0[4] = {v0.x, v0.y, v0.z, v0.w};
        float cn0[8] = {cnA0.x, cnA0.y, cnA0.z, cnA0.w, cnB0.x, cnB0.y, cnB0.z, cnB0.w};
#pragma unroll
        for (int k = 0; k < 4; k++) {
            float sa = fmaf(NEG2INV, __uint_as_float(w0[k] << 16), cn0[2 * k]);
            float sb = fmaf(NEG2INV, __uint_as_float(w0[k] & 0xFFFF0000u), cn0[2 * k + 1]);
            if (sa <= thresh) {
                int pos = atomicAdd(&scnt, 1);
                if (pos < 512) cand[pos] = j00 + 2 * k;
            }
            if (sb <= thresh) {
                int pos = atomicAdd(&scnt, 1);
                if (pos < 512) cand[pos] = j00 + 2 * k + 1;
            }
        }
        if (p2) {
            unsigned w1[4] = {v1.x, v1.y, v1.z, v1.w};
            float cn1[8] = {cnA1.x, cnA1.y, cnA1.z, cnA1.w, cnB1.x, cnB1.y, cnB1.z, cnB1.w};
#pragma unroll
            for (int k = 0; k < 4; k++) {
                float sa = fmaf(NEG2INV, __uint_as_float(w1[k] << 16), cn1[2 * k]);
                float sb = fmaf(NEG2INV, __uint_as_float(w1[k] & 0xFFFF0000u), cn1[2 * k + 1]);
                if (sa <= thresh) {
                    int pos = atomicAdd(&scnt, 1);
                    if (pos < 512) cand[pos] = j01 + 2 * k;
                }
                if (sb <= thresh) {
                    int pos = atomicAdd(&scnt, 1);
                    if (pos < 512) cand[pos] = j01 + 2 * k + 1;
                }
            }
        }
    }
    __syncthreads();
    int nc = scnt < 512 ? scnt : 512;

    unsigned long long best = ~0ull;
    const float* zr = g_zf + (size_t)row * E_DIM;
    for (int ci = wid; ci < nc; ci += 8) {
        const int j = cand[ci];
        const float* cbr = g_codebook + (size_t)j * E_DIM;
        float dot = 0.f;
#pragma unroll
        for (int d = lane; d < E_DIM; d += 32)
            dot = fmaf(zr[d], cbr[d], dot);
#pragma unroll
        for (int o = 16; o; o >>= 1) dot += __shfl_xor_sync(0xffffffffu, dot, o);
        float s = fmaf(-2.f, dot, g_cbnorm[j]);
        unsigned long long key = ((unsigned long long)fkey(s) << 32) | (unsigned)j;
        if (key < best) best = key;
    }
    if (lane == 0) wbest[wid] = best;
    __syncthreads();
    if (tid == 0) {
        unsigned long long k = wbest[0];
#pragma unroll
        for (int w = 1; w < 8; w++)
            if (wbest[w] < k) k = wbest[w];
        g_best[row] = k;
    }
}

// ======== L5: gather z_q, write min_idx, loss partials ========
__global__ __launch_bounds__(256) void k_gather(const float* __restrict__ z,
                                                float* __restrict__ out) {
    __shared__ int sidx[32];
    __shared__ float sred[256];
    const int blk = blockIdx.x;
    const int r0  = blk * 32;
    const int b   = r0 >> 10;
    const int t0  = r0 & 1023;
    const int tid = threadIdx.x;

    if (tid < 32) {
        unsigned long long key = g_best[r0 + tid];
        int idx = (int)(key & 0xffffffffull);
        sidx[tid] = idx;
        out[ZQ_ELEMS + r0 + tid] = (float)idx;
    }
    __syncthreads();

    const int t  = tid & 31;
    const int dl = tid >> 5;
    const int row = sidx[t];
    const float* cbr = g_codebook + (size_t)row * E_DIM;
    const size_t obase = (size_t)b * CT + t0 + t;
    float lacc = 0.f;
#pragma unroll 8
    for (int d = dl; d < E_DIM; d += 8) {
        float v  = cbr[d];
        float zt = z[obase + (size_t)d * T_SZ];
        float df = v - zt;
        lacc += df * df;
        out[obase + (size_t)d * T_SZ] = v;
    }
    sred[tid] = lacc;
    __syncthreads();
#pragma unroll
    for (int o = 128; o; o >>= 1) {
        if (tid < o) sred[tid] += sred[tid + o];
        __syncthreads();
    }
    if (tid == 0) g_partial[blk] = sred[0];
}

// ======== L6: finalize loss ========
__global__ void k_final(float* __restrict__ out) {
    __shared__ float sr[256];
    int tid = threadIdx.x;
    sr[tid] = g_partial[tid];
    __syncthreads();
#pragma unroll
    for (int o = 128; o; o >>= 1) {
        if (tid < o) sr[tid] += sr[tid + o];
        __syncthreads();
    }
    if (tid == 0)
        out[ZQ_ELEMS + ROWS] = sr[0] * 1.25f / (float)ZQ_ELEMS;
}

extern "C" void kernel_launch(void* const* d_in, const int* in_sizes, int n_in,
                              void* d_out, int out_size) {
    int i_z = -1, i_emb = -1, i_ad = -1, i_pw = -1, i_pb = -1;
    for (int i = 0; i < n_in; i++) {
        int s = in_sizes[i];
        if (s == ZQ_ELEMS) { if (i_z < 0) i_z = i; else i_emb = i; }
        else if (s == E_DIM * E_DIM) i_pw = i;
        else if (s == E_DIM)         i_pb = i;
        else if (s == B_SZ)          i_ad = i;
    }
    const float* z   = (const float*)d_in[i_z];
    const int*   ad  = (const int*)d_in[i_ad];
    const float* emb = (const float*)d_in[i_emb];
    const float* pw  = (const float*)d_in[i_pw];
    const float* pb  = (const float*)d_in[i_pb];
    float* out = (float*)d_out;

    cudaFuncSetAttribute(k_codebook_mma, cudaFuncAttributeMaxDynamicSharedMemorySize, SMEM_CB);
    cudaFuncSetAttribute(k_argmin_fp8,   cudaFuncAttributeMaxDynamicSharedMemorySize, SMEM_AG);

    k_split_all<<<EBLK + WBLK + ZBLK + SBLK, 256>>>(emb, pw, z, ad);        // 1
    k_codebook_mma<<<dim3(N_E / 128, E_DIM / 128), 256, SMEM_CB>>>(pb);     // 2
    k_argmin_fp8<<<dim3(64, 8), 256, SMEM_AG>>>();                          // 3
    k_scan<<<ROWS, 256>>>();                                                // 4 (profiled)
    k_gather<<<ROWS / 32, 256>>>(z, out);                                   // 5
    k_final<<<1, 256>>>(out);                                               // 6
}

// round 17
// speedup vs baseline: 1.0870x; 1.0108x over previous
#include <cuda_runtime.h>

#define N_E   8192
#define E_DIM 512
#define B_SZ  8
#define T_SZ  1024
#define ROWS  (B_SZ * T_SZ)
#define CT    (E_DIM * T_SZ)
#define ZQ_ELEMS (B_SZ * E_DIM * T_SZ)

#define PITCH 40                         // halves per SMEM row (bf16 codebook kernel)
#define ARR_BYTES   10240
#define MARGIN 1.0f
#define SZ_Z  16.0f
#define SZ_CB 1024.0f
#define NEG2INV (-1.220703125e-4f)       // -2/(16*1024)

#define CB_STAGE (4 * ARR_BYTES)
#define SMEM_CB  (4096 + 2 * CB_STAGE)

// fp8 screen: A resident (8 chunks x 128 rows x 80B), B 2-stage
#define A_CHUNK 10240
#define B_BASE  (8 * A_CHUNK)            // 81920
#define SMEM_AG (B_BASE + 2 * A_CHUNK)   // 102400

// -------- scratch --------
__device__ float g_codebook[N_E * E_DIM];
__device__ float g_cbnorm[N_E];
__device__ float g_zf[ROWS * E_DIM];
__device__ unsigned char g_cb8[N_E * E_DIM];       // e4m3, scale 1024
__device__ unsigned char g_z8[ROWS * E_DIM];       // e4m3, scale 16
__device__ unsigned short g_e_h[N_E * E_DIM];
__device__ unsigned short g_e_l[N_E * E_DIM];
__device__ unsigned short g_w_h[E_DIM * E_DIM];
__device__ unsigned short g_w_l[E_DIM * E_DIM];
__device__ unsigned short g_scores[(size_t)ROWS * N_E];  // bf16 SCREEN SCORES
__device__ unsigned g_bmin[ROWS];                  // fkey(min screen score)
__device__ unsigned long long g_best[ROWS];
__device__ float g_partial[ROWS / 32];
__device__ int g_lo[B_SZ], g_hi[B_SZ];

__device__ __forceinline__ unsigned int fkey(float f) {
    unsigned int u = __float_as_uint(f);
    return (u & 0x80000000u) ? ~u : (u | 0x80000000u);
}
__device__ __forceinline__ float fkey_inv(unsigned u) {
    return __uint_as_float((u & 0x80000000u) ? (u ^ 0x80000000u) : ~u);
}
__device__ __forceinline__ unsigned short f2bf(float x) {
    unsigned u = __float_as_uint(x);
    unsigned rb = 0x7FFFu + ((u >> 16) & 1u);
    return (unsigned short)((u + rb) >> 16);
}
__device__ __forceinline__ float bf2f(unsigned short h) {
    return __uint_as_float(((unsigned)h) << 16);
}
__device__ __forceinline__ unsigned char f2e4(float x) {
    unsigned short v;
    asm("cvt.rn.satfinite.e4m3x2.f32 %0, %1, %1;" : "=h"(v) : "f"(x));
    return (unsigned char)(v & 0xFF);
}
__device__ __forceinline__ unsigned smem_u32(const void* p) {
    unsigned a;
    asm("{ .reg .u64 t; cvta.to.shared.u64 t, %1; cvt.u32.u64 %0, t; }" : "=r"(a) : "l"(p));
    return a;
}
__device__ __forceinline__ void mma_bf16(float* c, const unsigned* a, const unsigned* b) {
    asm volatile(
        "mma.sync.aligned.m16n8k16.row.col.f32.bf16.bf16.f32 "
        "{%0,%1,%2,%3}, {%4,%5,%6,%7}, {%8,%9}, {%0,%1,%2,%3};"
        : "+f"(c[0]), "+f"(c[1]), "+f"(c[2]), "+f"(c[3])
        : "r"(a[0]), "r"(a[1]), "r"(a[2]), "r"(a[3]), "r"(b[0]), "r"(b[1]));
}
__device__ __forceinline__ void mma_fp8(float* c, const unsigned* a, const unsigned* b) {
    asm volatile(
        "mma.sync.aligned.m16n8k32.row.col.f32.e4m3.e4m3.f32 "
        "{%0,%1,%2,%3}, {%4,%5,%6,%7}, {%8,%9}, {%0,%1,%2,%3};"
        : "+f"(c[0]), "+f"(c[1]), "+f"(c[2]), "+f"(c[3])
        : "r"(a[0]), "r"(a[1]), "r"(a[2]), "r"(a[3]), "r"(b[0]), "r"(b[1]));
}
__device__ __forceinline__ void ldsm4(unsigned* r, unsigned addr) {
    asm volatile("ldmatrix.sync.aligned.m8n8.x4.shared.b16 {%0,%1,%2,%3}, [%4];"
                 : "=r"(r[0]), "=r"(r[1]), "=r"(r[2]), "=r"(r[3]) : "r"(addr));
}
__device__ __forceinline__ void cp16(unsigned dst, const void* src) {
    asm volatile("cp.async.cg.shared.global [%0], [%1], 16;" :: "r"(dst), "l"(src));
}
#define CP_COMMIT() asm volatile("cp.async.commit_group;" ::: "memory")
#define CP_WAIT0()  asm volatile("cp.async.wait_group 0;" ::: "memory")
#define BARQ(id) asm volatile("bar.sync %0, 64;" :: "r"(id) : "memory")

// ======== L1: fused splits + setup ========
#define EBLK (N_E * E_DIM / 4 / 256)     // 4096
#define WBLK (E_DIM * E_DIM / 4 / 256)   // 256
#define ZBLK 4096
#define SBLK (N_E / 256)                 // 32 (setup blocks)
__global__ __launch_bounds__(256) void k_split_all(const float* __restrict__ emb,
                                                   const float* __restrict__ pw,
                                                   const float* __restrict__ z,
                                                   const int* __restrict__ ad) {
    const int blk = blockIdx.x;
    const int tid = threadIdx.x;
    if (blk < EBLK) {
        int i = blk * 256 + tid;
        float4 v = ((const float4*)emb)[i];
        float xs[4] = {v.x, v.y, v.z, v.w};
        ushort4 h, l;
        unsigned short* hp = &h.x; unsigned short* lp = &l.x;
#pragma unroll
        for (int j = 0; j < 4; j++) {
            unsigned short hh = f2bf(xs[j]);
            hp[j] = hh; lp[j] = f2bf(xs[j] - bf2f(hh));
        }
        *(ushort4*)&g_e_h[(size_t)i * 4] = h;
        *(ushort4*)&g_e_l[(size_t)i * 4] = l;
    } else if (blk < EBLK + WBLK) {
        int i = (blk - EBLK) * 256 + tid;
        float4 v = ((const float4*)pw)[i];
        float xs[4] = {v.x, v.y, v.z, v.w};
        ushort4 h, l;
        unsigned short* hp = &h.x; unsigned short* lp = &l.x;
#pragma unroll
        for (int j = 0; j < 4; j++) {
            unsigned short hh = f2bf(xs[j]);
            hp[j] = hh; lp[j] = f2bf(xs[j] - bf2f(hh));
        }
        *(ushort4*)&g_w_h[(size_t)i * 4] = h;
        *(ushort4*)&g_w_l[(size_t)i * 4] = l;
    } else if (blk < EBLK + WBLK + ZBLK) {
        __shared__ float tile[32][33];
        const int zi = blk - (EBLK + WBLK);
        const int t0 = (zi & 31) * 32;
        const int k0 = ((zi >> 5) & 15) * 32;
        const int b  = zi >> 9;
        const int tx = tid & 31;
        const int ty = tid >> 5;
#pragma unroll
        for (int i = 0; i < 4; i++)
            tile[ty + 8 * i][tx] = z[(size_t)b * CT + (size_t)(k0 + ty + 8 * i) * T_SZ + t0 + tx];
        __syncthreads();
#pragma unroll
        for (int i = 0; i < 4; i++) {
            int tl = ty + 8 * i;
            float x = tile[tx][tl];
            size_t o = (size_t)(b * T_SZ + t0 + tl) * E_DIM + k0 + tx;
            g_zf[o] = x;
            g_z8[o] = f2e4(x * SZ_Z);
        }
    } else {
        int i = (blk - (EBLK + WBLK + ZBLK)) * 256 + tid;
        g_cbnorm[i] = 0.f;
        g_bmin[i & (ROWS - 1)] = 0xFFFFFFFFu;
        if (i == 0) {
            bool is64 = ((ad[1] | ad[3] | ad[5] | ad[7]) == 0);
            for (int b = 0; b < B_SZ; b++) {
                int dom = is64 ? ad[2 * b] : ad[b];
                int lo, hi;
                if (dom == 0)      { lo = 0;    hi = 2048; }
                else if (dom == 1) { lo = 2048; hi = 4096; }
                else if (dom == 2) { lo = 4096; hi = 8192; }
                else               { lo = 0;    hi = 8192; }
                g_lo[b] = lo; g_hi[b] = hi;
            }
        }
    }
}

// ======== L2: codebook (3-term split bf16 MMA, exact) — fully unrolled pipeline ========
__global__ __launch_bounds__(256, 2) void k_codebook_mma(const float* __restrict__ bias) {
    extern __shared__ char dsm[];
    const unsigned smb = smem_u32(dsm);
    float* bias_s = (float*)dsm;

    const int tid = threadIdx.x;
    const int lane = tid & 31, wid = tid >> 5;
    const int g = lane >> 2, t = lane & 3;
    const int warpM = wid >> 2, warpN = wid & 3;
    const int bx = blockIdx.x, by = blockIdx.y;

    if (tid < 128) bias_s[tid] = bias[by * 128 + tid];

    const int lrow = tid >> 1, lpart = tid & 1;
    const size_t aG = (size_t)(bx * 128 + lrow) * E_DIM + lpart * 16;
    const size_t bG = (size_t)(by * 128 + lrow) * E_DIM + lpart * 16;
    const unsigned dOff = (unsigned)(lrow * PITCH + lpart * 16) * 2;
    const unsigned stD = smb + 4096 + dOff;

    const int arow = (lane < 16) ? lane : lane - 16;
    const int akadd = (lane < 16) ? 0 : 8;
    const int brow = (lane & 7) + ((lane >= 16) ? 8 : 0);
    const int bkadd = ((lane >> 3) & 1) * 8;
    const unsigned baseAh = smb + 4096 + (unsigned)((warpM * 64 + arow) * PITCH + akadd) * 2;
    const unsigned baseBh = smb + 4096 + 2 * ARR_BYTES +
                            (unsigned)((warpN * 32 + brow) * PITCH + bkadd) * 2;

    float acc[4][4][4];
#pragma unroll
    for (int i = 0; i < 4; i++)
#pragma unroll
        for (int j = 0; j < 4; j++)
#pragma unroll
            for (int q = 0; q < 4; q++) acc[i][j][q] = 0.f;

    {
        cp16(stD,                  g_e_h + aG);      cp16(stD + 16,                  g_e_h + aG + 8);
        cp16(stD + ARR_BYTES,      g_e_l + aG);      cp16(stD + ARR_BYTES + 16,      g_e_l + aG + 8);
        cp16(stD + 2 * ARR_BYTES,  g_w_h + bG);      cp16(stD + 2 * ARR_BYTES + 16,  g_w_h + bG + 8);
        cp16(stD + 3 * ARR_BYTES,  g_w_l + bG);      cp16(stD + 3 * ARR_BYTES + 16,  g_w_l + bG + 8);
    }
    CP_COMMIT();

#pragma unroll
    for (int kc = 0; kc < 16; kc++) {
        const unsigned sOff = (kc & 1) * CB_STAGE;
        CP_WAIT0();
        __syncthreads();
        if (kc + 1 < 16) {
            const int kk = (kc + 1) * 32;
            const unsigned st = stD + ((kc + 1) & 1) * CB_STAGE;
            cp16(st,                  g_e_h + aG + kk);      cp16(st + 16,                  g_e_h + aG + kk + 8);
            cp16(st + ARR_BYTES,      g_e_l + aG + kk);      cp16(st + ARR_BYTES + 16,      g_e_l + aG + kk + 8);
            cp16(st + 2 * ARR_BYTES,  g_w_h + bG + kk);      cp16(st + 2 * ARR_BYTES + 16,  g_w_h + bG + kk + 8);
            cp16(st + 3 * ARR_BYTES,  g_w_l + bG + kk);      cp16(st + 3 * ARR_BYTES + 16,  g_w_l + bG + kk + 8);
        }
        CP_COMMIT();

#pragma unroll
        for (int ks = 0; ks < 2; ks++) {
            const unsigned kofs = ks * 32;
            unsigned bh[2][4], bl[2][4];
#pragma unroll
            for (int p = 0; p < 2; p++) {
                const unsigned ba = sOff + kofs + p * (16 * PITCH * 2);
                ldsm4(bh[p], baseBh + ba);
                ldsm4(bl[p], baseBh + ARR_BYTES + ba);
            }
#pragma unroll
            for (int mt = 0; mt < 4; mt++) {
                const unsigned aa = sOff + kofs + mt * (16 * PITCH * 2);
                unsigned ah[4], al[4];
                ldsm4(ah, baseAh + aa);
                ldsm4(al, baseAh + ARR_BYTES + aa);
#pragma unroll
                for (int nt = 0; nt < 4; nt++) {
                    const unsigned* bhp = &bh[nt >> 1][(nt & 1) * 2];
                    const unsigned* blp = &bl[nt >> 1][(nt & 1) * 2];
                    mma_bf16(acc[mt][nt], ah, bhp);
                    mma_bf16(acc[mt][nt], ah, blp);
                    mma_bf16(acc[mt][nt], al, bhp);
                }
            }
        }
    }

#pragma unroll
    for (int mt = 0; mt < 4; mt++) {
        float nrm0 = 0.f, nrm1 = 0.f;
#pragma unroll
        for (int nt = 0; nt < 4; nt++) {
            const int lcol = warpN * 32 + nt * 8 + 2 * t;
            const float b0 = bias_s[lcol], b1 = bias_s[lcol + 1];
            const int gc = by * 128 + lcol;
            const int r0 = bx * 128 + warpM * 64 + mt * 16 + g;
            float v0 = acc[mt][nt][0] + b0, v1 = acc[mt][nt][1] + b1;
            float v2 = acc[mt][nt][2] + b0, v3 = acc[mt][nt][3] + b1;
            size_t o0 = (size_t)r0 * E_DIM + gc;
            size_t o1 = (size_t)(r0 + 8) * E_DIM + gc;
            g_codebook[o0] = v0;         g_codebook[o0 + 1] = v1;
            g_codebook[o1] = v2;         g_codebook[o1 + 1] = v3;
            g_cb8[o0] = f2e4(v0 * SZ_CB); g_cb8[o0 + 1] = f2e4(v1 * SZ_CB);
            g_cb8[o1] = f2e4(v2 * SZ_CB); g_cb8[o1 + 1] = f2e4(v3 * SZ_CB);
            nrm0 += v0 * v0 + v1 * v1;
            nrm1 += v2 * v2 + v3 * v3;
        }
        nrm0 += __shfl_xor_sync(0xffffffffu, nrm0, 1);
        nrm0 += __shfl_xor_sync(0xffffffffu, nrm0, 2);
        nrm1 += __shfl_xor_sync(0xffffffffu, nrm1, 1);
        nrm1 += __shfl_xor_sync(0xffffffffu, nrm1, 2);
        if (t == 0) {
            const int r0 = bx * 128 + warpM * 64 + mt * 16 + g;
            atomicAdd(&g_cbnorm[r0], nrm0);
            atomicAdd(&g_cbnorm[r0 + 8], nrm1);
        }
    }
}

// ======== L3: fp8 screen — A resident, B quarter-local 2-stage; stores bf16 SCORES ========
__global__ __launch_bounds__(256, 2) void k_argmin_fp8() {
    extern __shared__ char dsm[];
    const unsigned smb = smem_u32(dsm);

    const int tid = threadIdx.x;
    const int lane = tid & 31, wid = tid >> 5;
    const int g = lane >> 2, t = lane & 3;
    const int warpM = wid >> 2, warpN = wid & 3;
    const int bx = blockIdx.x;
    const int b  = bx >> 3;
    const int c0 = blockIdx.y * 1024;
    if (c0 >= g_hi[b] || c0 + 1024 <= g_lo[b]) return;

    const int lrow = tid >> 1, lpart = tid & 1;
    const size_t aG = (size_t)(bx * 128 + lrow) * E_DIM + lpart * 32;
    const unsigned baseDA = smb + (unsigned)(lrow * 80 + lpart * 32);

    const int qbar = warpN + 1;
    const int qtid = ((wid >= 4) ? 32 : 0) + lane;
    const int brow_ld = warpN * 32 + (qtid >> 1);
    const int bhalf = qtid & 1;
    const size_t bGq = (size_t)(c0 + brow_ld) * E_DIM + bhalf * 32;
    const unsigned baseDB = smb + B_BASE + (unsigned)(brow_ld * 80 + bhalf * 32);

    const int arow = (lane < 16) ? lane : lane - 16;
    const int akadd = (lane < 16) ? 0 : 16;
    const int brow = (lane & 7) + ((lane >= 16) ? 8 : 0);
    const int bkadd = ((lane >> 3) & 1) * 16;
    const unsigned baseA = smb + (unsigned)((warpM * 64 + arow) * 80 + akadd);
    const unsigned baseB = smb + B_BASE + (unsigned)((warpN * 32 + brow) * 80 + bkadd);

    unsigned short* const sOut =
        g_scores + (size_t)(bx * 128 + warpM * 64 + g) * N_E + (c0 + warpN * 32 + 2 * t);
    const int colT = c0 + warpN * 32 + 2 * t;

    float acc[4][4][4];
#pragma unroll
    for (int i = 0; i < 4; i++)
#pragma unroll
        for (int j = 0; j < 4; j++)
#pragma unroll
            for (int q = 0; q < 4; q++) acc[i][j][q] = 0.f;

    float bestS[4][2];
#pragma unroll
    for (int i = 0; i < 4; i++) { bestS[i][0] = 3.4e38f; bestS[i][1] = 3.4e38f; }

#pragma unroll
    for (int c = 0; c < 8; c++) {
        cp16(baseDA + c * A_CHUNK,      g_z8 + aG + c * 64);
        cp16(baseDA + c * A_CHUNK + 16, g_z8 + aG + c * 64 + 16);
    }
    cp16(baseDB,      g_cb8 + bGq);
    cp16(baseDB + 16, g_cb8 + bGq + 16);
    CP_COMMIT();
    CP_WAIT0();
    __syncthreads();

    for (int it8 = 0; it8 < 64; it8 += 8) {
        const size_t bRow = bGq + (size_t)((it8 >> 3) * 128) * E_DIM;
        const size_t bRowN = bRow + (size_t)128 * E_DIM;
#pragma unroll
        for (int u = 0; u < 8; u++) {
            if (it8 + u > 0) {
                CP_WAIT0();
                BARQ(qbar);
            }
            if (it8 + u + 1 < 64) {
                const unsigned st = baseDB + (((u + 1) & 1)) * A_CHUNK;
                const int kk = ((u + 1) & 7) * 64;
                const size_t bS = (u == 7 ? bRowN : bRow) + kk;
                cp16(st,      g_cb8 + bS);
                cp16(st + 16, g_cb8 + bS + 16);
            }
            CP_COMMIT();

            const unsigned stgB = (u & 1) * A_CHUNK;
            const unsigned stgA = u * A_CHUNK;
#pragma unroll
            for (int ks = 0; ks < 2; ks++) {
                const int kofs = ks * 32;
                unsigned bh[2][4];
                ldsm4(bh[0], baseB + stgB + kofs);
                ldsm4(bh[1], baseB + stgB + 1280 + kofs);
#pragma unroll
                for (int mt = 0; mt < 4; mt++) {
                    unsigned ah[4];
                    ldsm4(ah, baseA + stgA + mt * 1280 + kofs);
#pragma unroll
                    for (int nt = 0; nt < 4; nt++)
                        mma_fp8(acc[mt][nt], ah, &bh[nt >> 1][(nt & 1) * 2]);
                }
            }

            if (u == 7) {
                const int ngOff = (it8 >> 3) * 128;
                float cn0[4], cn1[4];
#pragma unroll
                for (int nt = 0; nt < 4; nt++) {
                    cn0[nt] = __ldg(&g_cbnorm[colT + ngOff + nt * 8]);
                    cn1[nt] = __ldg(&g_cbnorm[colT + ngOff + nt * 8 + 1]);
                }
#pragma unroll
                for (int mt = 0; mt < 4; mt++) {
                    unsigned short* r0p = sOut + (size_t)(mt * 16) * N_E + ngOff;
                    unsigned short* r1p = r0p + (size_t)8 * N_E;
                    float m0 = bestS[mt][0], m1 = bestS[mt][1];
#pragma unroll
                    for (int nt = 0; nt < 4; nt++) {
                        float s0 = fmaf(NEG2INV, acc[mt][nt][0], cn0[nt]);
                        float s1 = fmaf(NEG2INV, acc[mt][nt][1], cn1[nt]);
                        float s2 = fmaf(NEG2INV, acc[mt][nt][2], cn0[nt]);
                        float s3 = fmaf(NEG2INV, acc[mt][nt][3], cn1[nt]);
                        m0 = fminf(m0, fminf(s0, s1));
                        m1 = fminf(m1, fminf(s2, s3));
                        ushort2 p01 = {f2bf(s0), f2bf(s1)};
                        ushort2 p23 = {f2bf(s2), f2bf(s3)};
                        *(ushort2*)(r0p + nt * 8) = p01;
                        *(ushort2*)(r1p + nt * 8) = p23;
                        acc[mt][nt][0] = 0.f; acc[mt][nt][1] = 0.f;
                        acc[mt][nt][2] = 0.f; acc[mt][nt][3] = 0.f;
                    }
                    bestS[mt][0] = m0; bestS[mt][1] = m1;
                }
            }
        }
    }

#pragma unroll
    for (int mt = 0; mt < 4; mt++)
#pragma unroll
        for (int h = 0; h < 2; h++) {
            float m = bestS[mt][h];
            m = fminf(m, __shfl_xor_sync(0xffffffffu, m, 1));
            m = fminf(m, __shfl_xor_sync(0xffffffffu, m, 2));
            if (t == 0)
                atomicMin(&g_bmin[bx * 128 + warpM * 64 + mt * 16 + h * 8 + g], fkey(m));
        }
}

// ======== L4: scan — collect on stored bf16 scores + exact fp32 rescore ========
__global__ __launch_bounds__(256) void k_scan() {
    __shared__ int   scnt;
    __shared__ int   cand[512];
    __shared__ unsigned long long wbest[8];

    const int row = blockIdx.x;
    const int tid = threadIdx.x;
    const int lane = tid & 31, wid = tid >> 5;
    const int b = row >> 10;
    const int lo = g_lo[b], hi = g_hi[b];

    const float thresh = fkey_inv(g_bmin[row]) + MARGIN;
    if (tid == 0) scnt = 0;
    __syncthreads();

    // collect: uint4 = 8 bf16 scores; no cbnorm needed
    const uint4* srow4 = (const uint4*)(g_scores + (size_t)row * N_E);
    for (int j8 = (lo >> 3) + tid; j8 < (hi >> 3); j8 += 256) {
        uint4 v = srow4[j8];
        const int j0 = j8 << 3;
        unsigned w[4] = {v.x, v.y, v.z, v.w};
#pragma unroll
        for (int k = 0; k < 4; k++) {
            float sa = __uint_as_float(w[k] << 16);
            float sb = __uint_as_float(w[k] & 0xFFFF0000u);
            if (sa <= thresh) {
                int pos = atomicAdd(&scnt, 1);
                if (pos < 512) cand[pos] = j0 + 2 * k;
            }
            if (sb <= thresh) {
                int pos = atomicAdd(&scnt, 1);
                if (pos < 512) cand[pos] = j0 + 2 * k + 1;
            }
        }
    }
    __syncthreads();
    int nc = scnt < 512 ? scnt : 512;

    unsigned long long best = ~0ull;
    const float* zr = g_zf + (size_t)row * E_DIM;
    for (int ci = wid; ci < nc; ci += 8) {
        const int j = cand[ci];
        const float* cbr = g_codebook + (size_t)j * E_DIM;
        float dot = 0.f;
#pragma unroll
        for (int d = lane; d < E_DIM; d += 32)
            dot = fmaf(zr[d], cbr[d], dot);
#pragma unroll
        for (int o = 16; o; o >>= 1) dot += __shfl_xor_sync(0xffffffffu, dot, o);
        float s = fmaf(-2.f, dot, g_cbnorm[j]);
        unsigned long long key = ((unsigned long long)fkey(s) << 32) | (unsigned)j;
        if (key < best) best = key;
    }
    if (lane == 0) wbest[wid] = best;
    __syncthreads();
    if (tid == 0) {
        unsigned long long k = wbest[0];
#pragma unroll
        for (int w = 1; w < 8; w++)
            if (wbest[w] < k) k = wbest[w];
        g_best[row] = k;
    }
}

// ======== L5: gather z_q, write min_idx, loss partials ========
__global__ __launch_bounds__(256) void k_gather(const float* __restrict__ z,
                                                float* __restrict__ out) {
    __shared__ int sidx[32];
    __shared__ float sred[256];
    const int blk = blockIdx.x;
    const int r0  = blk * 32;
    const int b   = r0 >> 10;
    const int t0  = r0 & 1023;
    const int tid = threadIdx.x;

    if (tid < 32) {
        unsigned long long key = g_best[r0 + tid];
        int idx = (int)(key & 0xffffffffull);
        sidx[tid] = idx;
        out[ZQ_ELEMS + r0 + tid] = (float)idx;
    }
    __syncthreads();

    const int t  = tid & 31;
    const int dl = tid >> 5;
    const int row = sidx[t];
    const float* cbr = g_codebook + (size_t)row * E_DIM;
    const size_t obase = (size_t)b * CT + t0 + t;
    float lacc = 0.f;
#pragma unroll 8
    for (int d = dl; d < E_DIM; d += 8) {
        float v  = cbr[d];
        float zt = z[obase + (size_t)d * T_SZ];
        float df = v - zt;
        lacc += df * df;
        out[obase + (size_t)d * T_SZ] = v;
    }
    sred[tid] = lacc;
    __syncthreads();
#pragma unroll
    for (int o = 128; o; o >>= 1) {
        if (tid < o) sred[tid] += sred[tid + o];
        __syncthreads();
    }
    if (tid == 0) g_partial[blk] = sred[0];
}

// ======== L6: finalize loss ========
__global__ void k_final(float* __restrict__ out) {
    __shared__ float sr[256];
    int tid = threadIdx.x;
    sr[tid] = g_partial[tid];
    __syncthreads();
#pragma unroll
    for (int o = 128; o; o >>= 1) {
        if (tid < o) sr[tid] += sr[tid + o];
        __syncthreads();
    }
    if (tid == 0)
        out[ZQ_ELEMS + ROWS] = sr[0] * 1.25f / (float)ZQ_ELEMS;
}

extern "C" void kernel_launch(void* const* d_in, const int* in_sizes, int n_in,
                              void* d_out, int out_size) {
    int i_z = -1, i_emb = -1, i_ad = -1, i_pw = -1, i_pb = -1;
    for (int i = 0; i < n_in; i++) {
        int s = in_sizes[i];
        if (s == ZQ_ELEMS) { if (i_z < 0) i_z = i; else i_emb = i; }
        else if (s == E_DIM * E_DIM) i_pw = i;
        else if (s == E_DIM)         i_pb = i;
        else if (s == B_SZ)          i_ad = i;
    }
    const float* z   = (const float*)d_in[i_z];
    const int*   ad  = (const int*)d_in[i_ad];
    const float* emb = (const float*)d_in[i_emb];
    const float* pw  = (const float*)d_in[i_pw];
    const float* pb  = (const float*)d_in[i_pb];
    float* out = (float*)d_out;

    cudaFuncSetAttribute(k_codebook_mma, cudaFuncAttributeMaxDynamicSharedMemorySize, SMEM_CB);
    cudaFuncSetAttribute(k_argmin_fp8,   cudaFuncAttributeMaxDynamicSharedMemorySize, SMEM_AG);

    k_split_all<<<EBLK + WBLK + ZBLK + SBLK, 256>>>(emb, pw, z, ad);        // 1
    k_codebook_mma<<<dim3(N_E / 128, E_DIM / 128), 256, SMEM_CB>>>(pb);     // 2
    k_argmin_fp8<<<dim3(64, 8), 256, SMEM_AG>>>();                          // 3
    k_scan<<<ROWS, 256>>>();                                                // 4 (profiled)
    k_gather<<<ROWS / 32, 256>>>(z, out);                                   // 5
    k_final<<<1, 256>>>(out);                                               // 6
}